// round 2
// baseline (speedup 1.0000x reference)
#include <cuda_runtime.h>
#include <math.h>

#define NT     250000
#define NNODE  20000
#define NREL   64
#define RPF    8
#define EMBD   64
#define NCLS   16
#define NRP    (NNODE * RPF)   // 160000

// ---------------- scratch (device globals; no allocation) ----------------
__device__ __align__(16) float d_l1[NT * RPF];        // 8 MB
__device__ __align__(16) float d_l2[NT * RPF];        // 8 MB
__device__ __align__(16) float d_S [NNODE * RPF];     // per-(o,r) l1 sums
__device__ __align__(16) float d_T [NNODE * RPF];     // per-(s,r) l2 sums
__device__ __align__(16) float d_colsum[NRP];
__device__ __align__(16) float d_rowsum[NRP];
__device__ __align__(16) float d_h [NNODE * EMBD];    // layer-1 accumulator
__device__ __align__(16) float d_g [NNODE * RPF * NCLS]; // g[o, rr, c]

// PTX ISA documented form: red.global.v4.f32.add [a], {b,c,d,e};
__device__ __forceinline__ void red_add_v4(float* addr, float a, float b, float c, float d) {
    asm volatile("red.global.v4.f32.add [%0], {%1, %2, %3, %4};"
                 :: "l"(addr), "f"(a), "f"(b), "f"(c), "f"(d) : "memory");
}

// ---------------- K0: init scratch, seed logits with bias2 ----------------
__global__ void k_init(float* __restrict__ logits, const float* __restrict__ bias2) {
    int i = blockIdx.x * blockDim.x + threadIdx.x;
    int stride = gridDim.x * blockDim.x;
    for (int j = i; j < NNODE * RPF; j += stride) { d_S[j] = 0.f; d_T[j] = 0.f; }
    for (int j = i; j < NRP; j += stride)         { d_colsum[j] = 0.f; d_rowsum[j] = 0.f; }
    for (int j = i; j < NNODE * EMBD; j += stride) d_h[j] = 0.f;
    for (int j = i; j < NNODE * NCLS; j += stride) logits[j] = bias2[j & 15];
}

// ---------------- K1: l1 = rm@W1+b1 ; l2 = softmax(rm@W2+b2) ; S,T sums ----
// One warp processes 16 edges. Lane = (r in [0,8), hc in [0,4)); each lane holds
// W columns for its r over a 16-wide rel chunk in registers.
__global__ void __launch_bounds__(256) k1_edge(
    const float* __restrict__ rm, const int* __restrict__ hrow,
    const int* __restrict__ vcol,
    const float* __restrict__ W1, const float* __restrict__ b1v,
    const float* __restrict__ W2, const float* __restrict__ b2v)
{
    int warp = (blockIdx.x * blockDim.x + threadIdx.x) >> 5;
    if (warp >= (NT / 16)) return;
    int lane = threadIdx.x & 31;
    int r  = lane & 7;
    int hc = lane >> 3;

    float w1[16], w2[16];
#pragma unroll
    for (int i = 0; i < 16; i++) {
        w1[i] = __ldg(&W1[(hc * 16 + i) * 8 + r]);
        w2[i] = __ldg(&W2[(hc * 16 + i) * 8 + r]);
    }
    float bb1 = __ldg(&b1v[r]);
    float bb2 = __ldg(&b2v[r]);

    int t0 = warp * 16;
    for (int e = 0; e < 16; e++) {
        int t = t0 + e;
        const float4* row = reinterpret_cast<const float4*>(rm + (size_t)t * 64 + hc * 16);
        float p1 = 0.f, p2 = 0.f;
#pragma unroll
        for (int q = 0; q < 4; q++) {
            float4 v = __ldg(&row[q]);
            p1 += v.x * w1[4*q] + v.y * w1[4*q+1] + v.z * w1[4*q+2] + v.w * w1[4*q+3];
            p2 += v.x * w2[4*q] + v.y * w2[4*q+1] + v.z * w2[4*q+2] + v.w * w2[4*q+3];
        }
        // all-reduce over the 4 rel-chunks (xor 8, 16 keeps r fixed)
        p1 += __shfl_xor_sync(0xffffffffu, p1, 8);
        p1 += __shfl_xor_sync(0xffffffffu, p1, 16);
        p2 += __shfl_xor_sync(0xffffffffu, p2, 8);
        p2 += __shfl_xor_sync(0xffffffffu, p2, 16);

        float l1v = p1 + bb1;
        float z   = p2 + bb2;
        // softmax across the 8 r-lanes (xor 1,2,4 stays inside the 8-group)
        float m = z;
        m = fmaxf(m, __shfl_xor_sync(0xffffffffu, m, 1));
        m = fmaxf(m, __shfl_xor_sync(0xffffffffu, m, 2));
        m = fmaxf(m, __shfl_xor_sync(0xffffffffu, m, 4));
        float ev = __expf(z - m);
        float se = ev;
        se += __shfl_xor_sync(0xffffffffu, se, 1);
        se += __shfl_xor_sync(0xffffffffu, se, 2);
        se += __shfl_xor_sync(0xffffffffu, se, 4);
        float l2v = ev / se;   // relu(softmax) == softmax (all positive)

        if (hc == 0) {
            int s = hrow[t];
            int o = vcol[t];
            d_l1[t * 8 + r] = l1v;
            d_l2[t * 8 + r] = l2v;
            atomicAdd(&d_S[o * 8 + r], l1v);
            atomicAdd(&d_T[s * 8 + r], l2v);
        }
    }
}

// ---------------- K2: scatter S/T into colsum/rowsum -----------------------
// colsum[j*r] += S[j,r] for r>=1; r==0 contributions are block-reduced into
// colsum[0] (every node maps there) to avoid a 20K-atomic hotspot.
__global__ void __launch_bounds__(256) k2_sums() {
    __shared__ float sc, sr;
    if (threadIdx.x == 0) { sc = 0.f; sr = 0.f; }
    __syncthreads();
    int i = blockIdx.x * blockDim.x + threadIdx.x;
    if (i < NNODE * RPF) {
        int r = i & 7;
        int j = i >> 3;
        float sv = d_S[i];
        float tv = d_T[i];
        if (r == 0) {
            atomicAdd(&sc, sv);
            atomicAdd(&sr, tv);
        } else {
            atomicAdd(&d_colsum[j * r], sv);
            atomicAdd(&d_rowsum[j * r], tv);
        }
    }
    __syncthreads();
    if (threadIdx.x == 0) {
        atomicAdd(&d_colsum[0], sc);
        atomicAdd(&d_rowsum[0], sr);
    }
}

// ---------------- K3: h[s] += sum_r (l1/colsum)[t,r] * W1flat[o*r] ---------
// 8 lanes per edge; lane l owns h-range [8l, 8l+8).
__global__ void __launch_bounds__(256) k3_layer1(
    const int* __restrict__ hrow, const int* __restrict__ vcol,
    const float* __restrict__ W)   // weights1 flat [160000 * 64]
{
    int gid = blockIdx.x * blockDim.x + threadIdx.x;
    int t = gid >> 3;
    bool valid = (t < NT);
    if (!valid) t = 0;
    int l = gid & 7;
    int lane = threadIdx.x & 31;

    int s = hrow[t];
    int o = vcol[t];
    float a = d_l1[t * 8 + l] / d_colsum[o * l];

    float acc0 = 0.f, acc1 = 0.f, acc2 = 0.f, acc3 = 0.f;
    float acc4 = 0.f, acc5 = 0.f, acc6 = 0.f, acc7 = 0.f;
#pragma unroll
    for (int r = 0; r < 8; r++) {
        float ar = __shfl_sync(0xffffffffu, a, (lane & 24) + r);
        const float4* wr = reinterpret_cast<const float4*>(W + (size_t)(o * r) * 64 + l * 8);
        float4 v0 = __ldg(&wr[0]);
        float4 v1 = __ldg(&wr[1]);
        acc0 += ar * v0.x; acc1 += ar * v0.y; acc2 += ar * v0.z; acc3 += ar * v0.w;
        acc4 += ar * v1.x; acc5 += ar * v1.y; acc6 += ar * v1.z; acc7 += ar * v1.w;
    }
    if (valid) {
        float* hp = d_h + s * 64 + l * 8;
        red_add_v4(hp,     acc0, acc1, acc2, acc3);
        red_add_v4(hp + 4, acc4, acc5, acc6, acc7);
    }
}

// ---------------- K4: g[node, rr, c] = relu(h+b1) @ W2cat  (20000x128x64) --
// Block computes a 128(node) x 128(rr*16+c) tile, K=64 in two 32-wide stages.
__global__ void __launch_bounds__(256) k4_gemm(
    const float* __restrict__ W2, const float* __restrict__ bias1)
{
    __shared__ float hs[32][129];
    __shared__ __align__(16) float ws[32][128];
    int m0 = blockIdx.x * 128;
    int tid = threadIdx.x;
    int tx = tid & 15;      // node lane
    int ty = tid >> 4;      // col group (8 cols each)

    float acc[8][8];
#pragma unroll
    for (int i = 0; i < 8; i++)
#pragma unroll
        for (int j = 0; j < 8; j++) acc[i][j] = 0.f;

    for (int kt = 0; kt < 2; kt++) {
        {   // h tile transposed, fused relu(h + bias1)
            int kk  = tid & 31;
            int nl0 = tid >> 5;
            float bv = __ldg(&bias1[kt * 32 + kk]);
#pragma unroll
            for (int it = 0; it < 16; it++) {
                int nl = nl0 + it * 8;
                int node = m0 + nl;
                float v = 0.f;
                if (node < NNODE) v = fmaxf(d_h[node * 64 + kt * 32 + kk] + bv, 0.f);
                hs[kk][nl] = v;
            }
        }
        {   // ws[k][rr*16+c] = W2[rr, kt*32+k, c]
            int n  = tid & 127;
            int kb = tid >> 7;
            int rr = n >> 4, c = n & 15;
#pragma unroll
            for (int it = 0; it < 16; it++) {
                int kk2 = kb + it * 2;
                ws[kk2][n] = __ldg(&W2[rr * 1024 + (kt * 32 + kk2) * 16 + c]);
            }
        }
        __syncthreads();
#pragma unroll
        for (int k = 0; k < 32; k++) {
            float av[8];
#pragma unroll
            for (int i = 0; i < 8; i++) av[i] = hs[k][tx + 16 * i];
            float4 b0 = *reinterpret_cast<const float4*>(&ws[k][ty * 8]);
            float4 b1 = *reinterpret_cast<const float4*>(&ws[k][ty * 8 + 4]);
            float bv[8] = {b0.x, b0.y, b0.z, b0.w, b1.x, b1.y, b1.z, b1.w};
#pragma unroll
            for (int i = 0; i < 8; i++)
#pragma unroll
                for (int j = 0; j < 8; j++) acc[i][j] += av[i] * bv[j];
        }
        __syncthreads();
    }
#pragma unroll
    for (int i = 0; i < 8; i++) {
        int node = m0 + tx + 16 * i;
        if (node < NNODE) {
            float4 v0 = make_float4(acc[i][0], acc[i][1], acc[i][2], acc[i][3]);
            float4 v1 = make_float4(acc[i][4], acc[i][5], acc[i][6], acc[i][7]);
            *reinterpret_cast<float4*>(d_g + node * 128 + ty * 8)     = v0;
            *reinterpret_cast<float4*>(d_g + node * 128 + ty * 8 + 4) = v1;
        }
    }
}

// ---------------- K5: logits[nn] += (l2/rowsum)[t,r] * g[o, rr, :] ---------
// 8 lanes per edge (lane = r). k = s*r; rr = k/20000; nn = k%20000.
// k==0 (r==0 or s==0) is block-reduced in smem to avoid the logits[0] hotspot.
__global__ void __launch_bounds__(256) k5_layer2(
    const int* __restrict__ hrow, const int* __restrict__ vcol,
    float* __restrict__ logits)
{
    __shared__ float sacc[16];
    if (threadIdx.x < 16) sacc[threadIdx.x] = 0.f;
    __syncthreads();

    int gid = blockIdx.x * blockDim.x + threadIdx.x;
    int t = gid >> 3;
    int r = gid & 7;
    if (t < NT) {
        int s = hrow[t];
        int o = vcol[t];
        float l2v = d_l2[t * 8 + r];
        int k = s * r;
        float b = l2v / fmaxf(d_rowsum[k], 1e-6f);
        int rbig = k / NNODE;
        int nn = k - rbig * NNODE;
        const float4* gp = reinterpret_cast<const float4*>(d_g + o * 128 + rbig * 16);
        float4 g0 = __ldg(&gp[0]);
        float4 g1 = __ldg(&gp[1]);
        float4 g2 = __ldg(&gp[2]);
        float4 g3 = __ldg(&gp[3]);
        if (k == 0) {
            atomicAdd(&sacc[0],  b * g0.x); atomicAdd(&sacc[1],  b * g0.y);
            atomicAdd(&sacc[2],  b * g0.z); atomicAdd(&sacc[3],  b * g0.w);
            atomicAdd(&sacc[4],  b * g1.x); atomicAdd(&sacc[5],  b * g1.y);
            atomicAdd(&sacc[6],  b * g1.z); atomicAdd(&sacc[7],  b * g1.w);
            atomicAdd(&sacc[8],  b * g2.x); atomicAdd(&sacc[9],  b * g2.y);
            atomicAdd(&sacc[10], b * g2.z); atomicAdd(&sacc[11], b * g2.w);
            atomicAdd(&sacc[12], b * g3.x); atomicAdd(&sacc[13], b * g3.y);
            atomicAdd(&sacc[14], b * g3.z); atomicAdd(&sacc[15], b * g3.w);
        } else {
            float* lp = logits + nn * 16;
            red_add_v4(lp,      b * g0.x, b * g0.y, b * g0.z, b * g0.w);
            red_add_v4(lp + 4,  b * g1.x, b * g1.y, b * g1.z, b * g1.w);
            red_add_v4(lp + 8,  b * g2.x, b * g2.y, b * g2.z, b * g2.w);
            red_add_v4(lp + 12, b * g3.x, b * g3.y, b * g3.z, b * g3.w);
        }
    }
    __syncthreads();
    if (threadIdx.x < 16) atomicAdd(&logits[threadIdx.x], sacc[threadIdx.x]);
}

// ---------------- launch ----------------------------------------------------
extern "C" void kernel_launch(void* const* d_in, const int* in_sizes, int n_in,
                              void* d_out, int out_size) {
    const float* rm    = (const float*)d_in[0];   // relation_matrix [NT,64]
    const int*   hrow  = (const int*)  d_in[1];   // hrow[t] = s_t for t < NT
    const int*   vcol  = (const int*)  d_in[4];   // vcol[t] = o_t for t < NT
    const float* W_l1  = (const float*)d_in[5];
    const float* b_l1  = (const float*)d_in[6];
    const float* W_l2  = (const float*)d_in[7];
    const float* b_l2  = (const float*)d_in[8];
    const float* wts1  = (const float*)d_in[9];   // [8,20000,64] flat
    const float* wts2  = (const float*)d_in[10];  // [8,64,16]
    const float* bias1 = (const float*)d_in[11];
    const float* bias2 = (const float*)d_in[12];
    float* logits = (float*)d_out;

    k_init<<<1280, 256>>>(logits, bias2);
    k1_edge<<<(NT / 16 * 32 + 255) / 256, 256>>>(rm, hrow, vcol, W_l1, b_l1, W_l2, b_l2);
    k2_sums<<<(NNODE * RPF + 255) / 256, 256>>>();
    k3_layer1<<<(NT * 8 + 255) / 256, 256>>>(hrow, vcol, wts1);
    k4_gemm<<<(NNODE + 127) / 128, 256>>>(wts2, bias1);
    k5_layer2<<<(NT * 8 + 255) / 256, 256>>>(hrow, vcol, logits);
}